// round 14
// baseline (speedup 1.0000x reference)
#include <cuda_runtime.h>
#include <cuda_fp16.h>
#include <cstdint>
#include <stdint.h>

#define BATCH 2
#define CH    256
#define CI    128
#define NPOS  8192
#define KT    64
#define NT    (NPOS/KT)

// ---------------- scratch (device globals; no allocation) ----------------
__device__ __align__(16) __half g_Wth[CI*CH];         // [ci][c] fp16
__device__ __align__(16) __half g_Wph[CI*CH];
__device__ __align__(16) __half g_Wgh[CI*CH];
__device__ __align__(16) __half g_Wwh[CH*CI];         // [o][ci] fp16
__device__ __align__(16) __half g_xh [BATCH*CH*NPOS]; // [b][c][n] fp16
__device__ __align__(16) __half g_Qhi[BATCH*NPOS*CI]; // [b][n][ci] (scaled by log2e)
__device__ __align__(16) __half g_Khi[BATCH*NPOS*CI]; // [b][m][ci]
__device__ __align__(16) __half g_Vh [BATCH*NPOS*CI]; // [b][m][ci]
__device__ __align__(16) __half g_Yth[BATCH*CI*NPOS]; // [b][ci][n] fp16
__device__ float g_WY[BATCH*CH*NPOS];   // [b][o][n]
__device__ float g_mean[CH];
__device__ float g_rstd[CH];

// ---------------- helpers (baseline ISA only) ----------------
__device__ __forceinline__ uint32_t smem_u32(const void* p) {
    uint32_t a;
    asm("{ .reg .u64 t; cvta.to.shared.u64 t, %1; cvt.u32.u64 %0, t; }" : "=r"(a) : "l"(p));
    return a;
}
__device__ __forceinline__ void cp16(uint32_t d, const void* s) {
    asm volatile("cp.async.cg.shared.global [%0], [%1], 16;" :: "r"(d), "l"(s));
}
__device__ __forceinline__ void cp_commit()   { asm volatile("cp.async.commit_group;" ::: "memory"); }
__device__ __forceinline__ void cp_wait0()    { asm volatile("cp.async.wait_group 0;" ::: "memory"); }
__device__ __forceinline__ void cp_wait1()    { asm volatile("cp.async.wait_group 1;" ::: "memory"); }

__device__ __forceinline__ void ldm4(uint32_t& r0, uint32_t& r1, uint32_t& r2, uint32_t& r3, uint32_t a) {
    asm volatile("ldmatrix.sync.aligned.m8n8.x4.shared.b16 {%0,%1,%2,%3}, [%4];"
                 : "=r"(r0), "=r"(r1), "=r"(r2), "=r"(r3) : "r"(a));
}
__device__ __forceinline__ void ldm4t(uint32_t& r0, uint32_t& r1, uint32_t& r2, uint32_t& r3, uint32_t a) {
    asm volatile("ldmatrix.sync.aligned.m8n8.x4.trans.shared.b16 {%0,%1,%2,%3}, [%4];"
                 : "=r"(r0), "=r"(r1), "=r"(r2), "=r"(r3) : "r"(a));
}
#define MMA16816(c, a0,a1,a2,a3, b0,b1) \
    asm volatile("mma.sync.aligned.m16n8k16.row.col.f32.f16.f16.f32 " \
                 "{%0,%1,%2,%3},{%4,%5,%6,%7},{%8,%9},{%0,%1,%2,%3};" \
                 : "+f"((c)[0]), "+f"((c)[1]), "+f"((c)[2]), "+f"((c)[3]) \
                 : "r"(a0), "r"(a1), "r"(a2), "r"(a3), "r"(b0), "r"(b1))

__device__ __forceinline__ float ex2f(float x) {
    float r; asm("ex2.approx.f32 %0, %1;" : "=f"(r) : "f"(x)); return r;
}
__device__ __forceinline__ uint32_t packh2(float lo, float hi) {
    __half2 h = __floats2half2_rn(lo, hi);
    return *reinterpret_cast<uint32_t*>(&h);
}

// smem layout for attn (bytes)
#define QPITCH_B   272                      // 136 halves per row
#define QMAT_B     (128*QPITCH_B)           // 34816
#define KMAT_B     (64*QPITCH_B)            // 17408
#define KVBUF_B    (2*KMAT_B)               // KHI,V = 34816
#define SM_KV      QMAT_B                   // KV ring (4 slots)
#define P_PITCH    144                      // 64 halves + 16B pad
#define P_BUF_B    (128*P_PITCH)            // 18432
#define SM_P       (QMAT_B + 4*KVBUF_B)     // 174080
#define SM_LROW    (SM_P + 2*P_BUF_B)       // 210944
#define DSM_BYTES  (SM_LROW + 512)          // 211456

// ---------------- K0a: weight fp16 conversion ----------------
__global__ __launch_bounds__(256) void cvt_weights(
    const float* __restrict__ Wt, const float* __restrict__ Wp,
    const float* __restrict__ Wg, const float* __restrict__ Ww)
{
    int idx = blockIdx.x * 256 + threadIdx.x;
    int which = blockIdx.y;
    if (which == 0)      g_Wth[idx] = __float2half_rn(Wt[idx]);
    else if (which == 1) g_Wph[idx] = __float2half_rn(Wp[idx]);
    else if (which == 2) g_Wgh[idx] = __float2half_rn(Wg[idx]);
    else                 g_Wwh[idx] = __float2half_rn(Ww[idx]);
}

// ---------------- K0b: x -> fp16 ----------------
__global__ __launch_bounds__(256) void xcvt(const float* __restrict__ x)
{
    int i4 = blockIdx.x * 256 + threadIdx.x;
    float4 v = ((const float4*)x)[i4];
    __half2 a = __floats2half2_rn(v.x, v.y);
    __half2 b = __floats2half2_rn(v.z, v.w);
    uint2 u;
    u.x = *reinterpret_cast<uint32_t*>(&a);
    u.y = *reinterpret_cast<uint32_t*>(&b);
    ((uint2*)g_xh)[i4] = u;
}

// ---------------- K1: QKV projection via mma.sync ----------------
#define QK_WPITCH 528
#define QK_XPITCH 272
#define QK_WSH_B  (128*QK_WPITCH)   // 67584
#define QK_XSH_B  (256*QK_XPITCH)   // 69632
#define QK_DSM    (QK_WSH_B + QK_XSH_B)  // 137216

__global__ __launch_bounds__(256, 1) void qkv_mma(
    const float* __restrict__ bt, const float* __restrict__ bp,
    const float* __restrict__ bg)
{
    extern __shared__ __align__(16) char dsm[];
    const uint32_t wsh = smem_u32(dsm);
    const uint32_t xsh = wsh + QK_WSH_B;

    const int n0  = blockIdx.x * 128;
    const int b   = blockIdx.y;
    const int sel = blockIdx.z;
    const __half* Wh   = (sel == 0) ? g_Wth : (sel == 1) ? g_Wph : g_Wgh;
    const float*  bias = (sel == 0) ? bt : (sel == 1) ? bp : bg;
    const __half* xb   = &g_xh[(size_t)b * CH * NPOS];

    const int tid = threadIdx.x;
    const int w   = tid >> 5;
    const int lane = tid & 31;
    const int g   = lane >> 2;
    const int tq  = lane & 3;

#pragma unroll
    for (int it = 0; it < 16; it++) {
        int idx = tid + it * 256;
        int r = idx >> 5, s = idx & 31;
        cp16(wsh + (uint32_t)(r * QK_WPITCH + s * 16), Wh + (size_t)r * CH + s * 8);
    }
#pragma unroll
    for (int it = 0; it < 16; it++) {
        int idx = tid + it * 256;
        int r = idx >> 4, s = idx & 15;
        cp16(xsh + (uint32_t)(r * QK_XPITCH + s * 16), xb + (size_t)r * NPOS + n0 + s * 8);
    }
    cp_commit();
    cp_wait0();
    __syncthreads();

    const uint32_t a_base = wsh + (uint32_t)(16 * w + (lane & 15)) * QK_WPITCH
                          + (uint32_t)((lane >> 4) & 1) * 16;
    const int v_row = (lane & 7) + (((lane >> 3) & 1) << 3);
    const uint32_t v_c8 = (uint32_t)((lane >> 4) & 1) * 16;

    float c[16][4];
#pragma unroll
    for (int j = 0; j < 16; j++)
#pragma unroll
        for (int q = 0; q < 4; q++) c[j][q] = 0.f;

#pragma unroll
    for (int ks = 0; ks < 16; ks++) {
        uint32_t a0, a1, a2, a3;
        ldm4(a0, a1, a2, a3, a_base + (uint32_t)ks * 32);
        const uint32_t xrow = xsh + (uint32_t)(16 * ks + v_row) * QK_XPITCH + v_c8;
#pragma unroll
        for (int f = 0; f < 8; f++) {
            uint32_t b0, b1, b2, b3;
            ldm4t(b0, b1, b2, b3, xrow + (uint32_t)(f * 16) * 2);
            MMA16816(c[2*f],   a0, a1, a2, a3, b0, b1);
            MMA16816(c[2*f+1], a0, a1, a2, a3, b2, b3);
        }
    }

    __syncthreads();

    const float scale = (sel == 0) ? 1.4426950408889634f : 1.0f;
    const int ci0 = 16 * w + g, ci1 = ci0 + 8;
    const float b0v = bias[ci0], b1v = bias[ci1];
    __half* sT = (__half*)dsm;        // [128 n][136 halves pitch]
#pragma unroll
    for (int j = 0; j < 16; j++) {
        int n = (j >> 1) * 16 + (j & 1) * 8 + 2 * tq;
        sT[n * 136 + ci0]       = __float2half_rn((c[j][0] + b0v) * scale);
        sT[(n + 1) * 136 + ci0] = __float2half_rn((c[j][1] + b0v) * scale);
        sT[n * 136 + ci1]       = __float2half_rn((c[j][2] + b1v) * scale);
        sT[(n + 1) * 136 + ci1] = __float2half_rn((c[j][3] + b1v) * scale);
    }
    __syncthreads();

    __half* dst = ((sel == 0) ? g_Qhi : (sel == 1) ? g_Khi : g_Vh)
                + ((size_t)b * NPOS + n0) * CI;
#pragma unroll
    for (int it = 0; it < 8; it++) {
        int idx = tid + it * 256;
        int r = idx >> 4, s = idx & 15;
        *(uint4*)&dst[(size_t)r * CI + s * 8] = *(uint4*)&sT[r * 136 + s * 8];
    }
}

// ---------------- K2: warp-specialized flash attention ----------------
// grid (64, 2), 512 threads: warps 0-7 = S-producers, 8-15 = PV-consumers.
__global__ __launch_bounds__(512, 1) void attn_kernel()
{
    extern __shared__ __align__(16) char dsm[];
    const uint32_t tb  = smem_u32(dsm);
    const uint32_t kvb = tb + SM_KV;
    const uint32_t pbb = tb + SM_P;
    float* lrow = (float*)(dsm + SM_LROW);

    const int b   = blockIdx.y;
    const int n0  = blockIdx.x * 128;
    const int tid = threadIdx.x;
    const int w   = tid >> 5;        // 0..15
    const int lane = tid & 31;
    const int g   = lane >> 2;
    const int tq  = lane & 3;
    const bool isS = (w < 8);
    const int wq  = w & 7;           // q-row group (rows 16*wq..16*wq+15)

    // per-lane ldmatrix addressing
    const uint32_t qa_off = (uint32_t)(16 * wq + (lane & 15)) * QPITCH_B
                          + (uint32_t)((lane >> 4) & 1) * 16;   // Q A-frags
    const int b_row = (lane & 7) + ((lane >> 4) << 3);          // K B-frags
    const uint32_t b_k8 = (uint32_t)((lane >> 3) & 1) * 16;
    const int v_row = (lane & 7) + (((lane >> 3) & 1) << 3);    // V trans B-frags
    const uint32_t v_c8 = (uint32_t)((lane >> 4) & 1) * 16;
    const uint32_t pa_off = (uint32_t)(16 * wq + (lane & 15)) * P_PITCH
                          + (uint32_t)((lane >> 4) & 1) * 16;   // P A-frags

    const __half* khg = &g_Khi[(size_t)b * NPOS * CI];
    const __half* vg  = &g_Vh [(size_t)b * NPOS * CI];

    auto load_tile = [&](int t, int slot) {
        const int m0 = t * KT;
        const uint32_t kb = kvb + (uint32_t)slot * KVBUF_B;
#pragma unroll
        for (int it = 0; it < 4; it++) {
            int idx = tid + it * 512;
            int mat = idx >> 10;
            int r   = (idx & 1023) >> 4;
            int seg = idx & 15;
            const __half* src = (mat == 0 ? khg : vg) + ((size_t)(m0 + r)) * CI + seg * 8;
            cp16(kb + (uint32_t)(mat * KMAT_B + r * QPITCH_B + seg * 16), src);
        }
    };

    // prologue: Q + tile0 (group A), tile1 (group B)
    {
        const __half* qh = &g_Qhi[((size_t)b * NPOS + n0) * CI];
#pragma unroll
        for (int it = 0; it < 4; it++) {
            int idx = tid + it * 512;
            int r   = idx >> 4;
            int seg = idx & 15;
            cp16(tb + (uint32_t)(r * QPITCH_B + seg * 16), qh + (size_t)r * CI + seg * 8);
        }
    }
    load_tile(0, 0);
    cp_commit();
    load_tile(1, 1);
    cp_commit();

    float O[16][4];
#pragma unroll
    for (int i = 0; i < 16; i++)
#pragma unroll
        for (int j = 0; j < 4; j++) O[i][j] = 0.f;
    float lsum0 = 0.f, lsum1 = 0.f;

#pragma unroll 1
    for (int t = 0; t < NT; t++) {
        if (t + 1 < NT) cp_wait1(); else cp_wait0();
        __syncthreads();
        if (t + 2 < NT) { load_tile(t + 2, (t + 2) & 3); cp_commit(); }

        if (isS) {
            // ---- S(t) = Q x K(t), exp2, write P(t) ----
            const uint32_t kb = kvb + (uint32_t)(t & 3) * KVBUF_B;
            float c[8][4];
#pragma unroll
            for (int i = 0; i < 8; i++)
#pragma unroll
                for (int j = 0; j < 4; j++) c[i][j] = 0.f;
#pragma unroll
            for (int k8 = 0; k8 < 8; k8++) {
                uint32_t a0, a1, a2, a3;
                ldm4(a0, a1, a2, a3, tb + qa_off + (uint32_t)k8 * 32);
#pragma unroll
                for (int nj = 0; nj < 4; nj++) {
                    uint32_t b0, b1, b2, b3;
                    ldm4(b0, b1, b2, b3, kb + (uint32_t)(nj * 16 + b_row) * QPITCH_B
                                            + (uint32_t)k8 * 32 + b_k8);
                    MMA16816(c[2*nj],   a0, a1, a2, a3, b0, b1);
                    MMA16816(c[2*nj+1], a0, a1, a2, a3, b2, b3);
                }
            }
            const uint32_t Pw = pbb + (uint32_t)(t & 1) * P_BUF_B;
            const int row0 = 16 * wq + g;
#pragma unroll
            for (int j = 0; j < 8; j++) {
                float e0 = ex2f(c[j][0]), e1 = ex2f(c[j][1]);
                float e2 = ex2f(c[j][2]), e3 = ex2f(c[j][3]);
                lsum0 += e0 + e1;
                lsum1 += e2 + e3;
                int colb = (j >> 1) * 16 + (j & 1) * 8 + 2 * tq;   // halves
                *(uint32_t*)(dsm + (Pw - tb) + row0 * P_PITCH + colb * 2)       = packh2(e0, e1);
                *(uint32_t*)(dsm + (Pw - tb) + (row0 + 8) * P_PITCH + colb * 2) = packh2(e2, e3);
            }
        } else if (t > 0) {
            // ---- PV(t-1) ----
            const uint32_t Pr = pbb + (uint32_t)((t - 1) & 1) * P_BUF_B;
            const uint32_t vb = kvb + (uint32_t)((t - 1) & 3) * KVBUF_B + KMAT_B;
#pragma unroll
            for (int kk = 0; kk < 4; kk++) {
                uint32_t a0, a1, a2, a3;
                ldm4(a0, a1, a2, a3, Pr + pa_off + (uint32_t)kk * 32);
                const uint32_t vrow_off = (uint32_t)(kk * 16 + v_row) * QPITCH_B;
#pragma unroll
                for (int p = 0; p < 8; p++) {
                    uint32_t b0, b1, b2, b3;
                    ldm4t(b0, b1, b2, b3, vb + vrow_off + (uint32_t)(p * 16) * 2 + v_c8);
                    MMA16816(O[2*p],   a0, a1, a2, a3, b0, b1);
                    MMA16816(O[2*p+1], a0, a1, a2, a3, b2, b3);
                }
            }
        }
    }

    // ---- final phase: PV(NT-1) + lsum publication ----
    __syncthreads();
    if (isS) {
        lsum0 += __shfl_xor_sync(0xffffffffu, lsum0, 1);
        lsum0 += __shfl_xor_sync(0xffffffffu, lsum0, 2);
        lsum1 += __shfl_xor_sync(0xffffffffu, lsum1, 1);
        lsum1 += __shfl_xor_sync(0xffffffffu, lsum1, 2);
        if (tq == 0) {
            lrow[16 * wq + g]     = lsum0;
            lrow[16 * wq + g + 8] = lsum1;
        }
    } else {
        const int t = NT;  // consume P(NT-1)
        const uint32_t Pr = pbb + (uint32_t)((t - 1) & 1) * P_BUF_B;
        const uint32_t vb = kvb + (uint32_t)((t - 1) & 3) * KVBUF_B + KMAT_B;
#pragma unroll
        for (int kk = 0; kk < 4; kk++) {
            uint32_t a0, a1, a2, a3;
            ldm4(a0, a1, a2, a3, Pr + pa_off + (uint32_t)kk * 32);
            const uint32_t vrow_off = (uint32_t)(kk * 16 + v_row) * QPITCH_B;
#pragma unroll
            for (int p = 0; p < 8; p++) {
                uint32_t b0, b1, b2, b3;
                ldm4t(b0, b1, b2, b3, vb + vrow_off + (uint32_t)(p * 16) * 2 + v_c8);
                MMA16816(O[2*p],   a0, a1, a2, a3, b0, b1);
                MMA16816(O[2*p+1], a0, a1, a2, a3, b2, b3);
            }
        }
    }
    __syncthreads();

    // ---- PV-warps scatter O/l into sO (overlays Q + KV slot0 region; safe now) ----
    float* sO = (float*)dsm;     // [128][132] floats, 67584B
    if (!isS) {
        const float linv0 = 1.f / lrow[16 * wq + g];
        const float linv1 = 1.f / lrow[16 * wq + g + 8];
#pragma unroll
        for (int p = 0; p < 16; p++) {
            int col = p * 8 + 2 * tq;
            sO[(16 * wq + g) * 132 + col]       = O[p][0] * linv0;
            sO[(16 * wq + g) * 132 + col + 1]   = O[p][1] * linv0;
            sO[(16 * wq + g + 8) * 132 + col]   = O[p][2] * linv1;
            sO[(16 * wq + g + 8) * 132 + col+1] = O[p][3] * linv1;
        }
    }
    __syncthreads();

    if (tid < 256) {
        const int ci   = tid >> 1;
        const int half = tid & 1;
        __half* dst = &g_Yth[((size_t)b * CI + ci) * NPOS + n0 + 64 * half];
#pragma unroll
        for (int r4 = 0; r4 < 16; r4++) {
            int r = 64 * half + r4 * 4;
            __half2 h01 = __floats2half2_rn(sO[(r + 0) * 132 + ci], sO[(r + 1) * 132 + ci]);
            __half2 h23 = __floats2half2_rn(sO[(r + 2) * 132 + ci], sO[(r + 3) * 132 + ci]);
            *(__half2*)&dst[r4 * 4]     = h01;
            *(__half2*)&dst[r4 * 4 + 2] = h23;
        }
    }
}

// ---------------- K3: output projection wy = Ww.y + bw via mma.sync ----------------
#define WY_WPITCH 272
#define WY_YPITCH 272
#define WY_WSH_B  (256*WY_WPITCH)   // 69632
#define WY_YSH_B  (128*WY_YPITCH)   // 34816
#define WY_DSM    (WY_WSH_B + WY_YSH_B)

__global__ __launch_bounds__(256, 1) void wy_kernel(const float* __restrict__ bw)
{
    extern __shared__ __align__(16) char dsm[];
    const uint32_t wsh = smem_u32(dsm);
    const uint32_t ysh = wsh + WY_WSH_B;

    const int n0 = blockIdx.x * 128;
    const int b  = blockIdx.y;
    const int tid = threadIdx.x;
    const int w   = tid >> 5;
    const int lane = tid & 31;
    const int g   = lane >> 2;
    const int tq  = lane & 3;

#pragma unroll
    for (int it = 0; it < 16; it++) {
        int idx = tid + it * 256;
        int r = idx >> 4, seg = idx & 15;
        cp16(wsh + (uint32_t)(r * WY_WPITCH + seg * 16), &g_Wwh[(size_t)r * CI + seg * 8]);
    }
    {
        const __half* yg = &g_Yth[(size_t)b * CI * NPOS + n0];
#pragma unroll
        for (int it = 0; it < 8; it++) {
            int idx = tid + it * 256;
            int r = idx >> 4, seg = idx & 15;
            cp16(ysh + (uint32_t)(r * WY_YPITCH + seg * 16), yg + (size_t)r * NPOS + seg * 8);
        }
    }
    cp_commit();
    cp_wait0();
    __syncthreads();

    const uint32_t a_base = wsh + (uint32_t)(32 * w + (lane & 15)) * WY_WPITCH
                          + (uint32_t)((lane >> 4) & 1) * 16;
    const int v_row = (lane & 7) + (((lane >> 3) & 1) << 3);
    const uint32_t v_c8 = (uint32_t)((lane >> 4) & 1) * 16;

    float c[2][16][4];
#pragma unroll
    for (int m = 0; m < 2; m++)
#pragma unroll
        for (int j = 0; j < 16; j++)
#pragma unroll
            for (int q = 0; q < 4; q++) c[m][j][q] = 0.f;

#pragma unroll
    for (int ks = 0; ks < 8; ks++) {
        uint32_t a0[4], a1[4];
        ldm4(a0[0], a0[1], a0[2], a0[3], a_base + (uint32_t)ks * 32);
        ldm4(a1[0], a1[1], a1[2], a1[3], a_base + 16u * WY_WPITCH + (uint32_t)ks * 32);
        const uint32_t yrow = ysh + (uint32_t)(16 * ks + v_row) * WY_YPITCH + v_c8;
#pragma unroll
        for (int f = 0; f < 8; f++) {
            uint32_t b0, b1, b2, b3;
            ldm4t(b0, b1, b2, b3, yrow + (uint32_t)(f * 16) * 2);
            MMA16816(c[0][2*f],   a0[0], a0[1], a0[2], a0[3], b0, b1);
            MMA16816(c[0][2*f+1], a0[0], a0[1], a0[2], a0[3], b2, b3);
            MMA16816(c[1][2*f],   a1[0], a1[1], a1[2], a1[3], b0, b1);
            MMA16816(c[1][2*f+1], a1[0], a1[1], a1[2], a1[3], b2, b3);
        }
    }

#pragma unroll
    for (int m = 0; m < 2; m++) {
        const int o0 = 32 * w + 16 * m;
        const float bias0 = bw[o0 + g];
        const float bias1 = bw[o0 + g + 8];
        float* d0 = &g_WY[((size_t)b * CH + o0 + g) * NPOS + n0];
        float* d1 = &g_WY[((size_t)b * CH + o0 + g + 8) * NPOS + n0];
#pragma unroll
        for (int j = 0; j < 16; j++) {
            int nc = 8 * j + 2 * tq;
            *(float2*)&d0[nc] = make_float2(c[m][j][0] + bias0, c[m][j][1] + bias0);
            *(float2*)&d1[nc] = make_float2(c[m][j][2] + bias1, c[m][j][3] + bias1);
        }
    }
}

// ---------------- K4: per-channel BN stats (single pass) ----------------
__global__ __launch_bounds__(256) void bnstats_kernel()
{
    const int o = blockIdx.x;
    const int tid = threadIdx.x;
    __shared__ float red[256];
    __shared__ float red2[256];

    float s = 0.f, sq = 0.f;
    for (int b = 0; b < BATCH; b++) {
        const float* p = &g_WY[((size_t)b * CH + o) * NPOS];
        for (int i = tid; i < NPOS; i += 256) {
            float v = p[i];
            s += v; sq += v * v;
        }
    }
    red[tid] = s; red2[tid] = sq; __syncthreads();
    for (int st = 128; st; st >>= 1) {
        if (tid < st) { red[tid] += red[tid + st]; red2[tid] += red2[tid + st]; }
        __syncthreads();
    }
    if (tid == 0) {
        float mean = red[0] / (float)(BATCH * NPOS);
        float var  = red2[0] / (float)(BATCH * NPOS) - mean * mean;
        g_mean[o] = mean;
        g_rstd[o] = rsqrtf(var + 1e-5f);
    }
}

// ---------------- K5: normalize + affine + residual ----------------
__global__ __launch_bounds__(256) void finalize_kernel(
    const float* __restrict__ x, const float* __restrict__ gamma,
    const float* __restrict__ beta, float* __restrict__ out)
{
    int i4 = blockIdx.x * 256 + threadIdx.x;
    int ch = (i4 >> 11) & (CH - 1);
    float sc = g_rstd[ch] * gamma[ch];
    float sh = beta[ch] - g_mean[ch] * sc;
    float4 w  = ((const float4*)g_WY)[i4];
    float4 xv = ((const float4*)x)[i4];
    float4 o;
    o.x = w.x * sc + sh + xv.x;
    o.y = w.y * sc + sh + xv.y;
    o.z = w.z * sc + sh + xv.z;
    o.w = w.w * sc + sh + xv.w;
    ((float4*)out)[i4] = o;
}

// ---------------- launch ----------------
extern "C" void kernel_launch(void* const* d_in, const int* in_sizes, int n_in,
                              void* d_out, int out_size)
{
    (void)in_sizes; (void)n_in; (void)out_size;
    const float* x     = (const float*)d_in[0];
    const float* Wt    = (const float*)d_in[1];
    const float* bt    = (const float*)d_in[2];
    const float* Wp    = (const float*)d_in[3];
    const float* bp    = (const float*)d_in[4];
    const float* Wg    = (const float*)d_in[5];
    const float* bg    = (const float*)d_in[6];
    const float* Ww    = (const float*)d_in[7];
    const float* bw    = (const float*)d_in[8];
    const float* gamma = (const float*)d_in[9];
    const float* beta  = (const float*)d_in[10];
    float* out = (float*)d_out;

    cvt_weights<<<dim3(128, 4), 256>>>(Wt, Wp, Wg, Ww);
    xcvt<<<(BATCH * CH * NPOS / 4) / 256, 256>>>(x);

    cudaFuncSetAttribute(qkv_mma, cudaFuncAttributeMaxDynamicSharedMemorySize, QK_DSM);
    qkv_mma<<<dim3(NPOS / 128, BATCH, 3), 256, QK_DSM>>>(bt, bp, bg);

    cudaFuncSetAttribute(attn_kernel, cudaFuncAttributeMaxDynamicSharedMemorySize, DSM_BYTES);
    attn_kernel<<<dim3(NPOS / 128, BATCH), 512, DSM_BYTES>>>();

    cudaFuncSetAttribute(wy_kernel, cudaFuncAttributeMaxDynamicSharedMemorySize, WY_DSM);
    wy_kernel<<<dim3(NPOS / 128, BATCH), 256, WY_DSM>>>(bw);

    bnstats_kernel<<<CH, 256>>>();
    finalize_kernel<<<(BATCH * CH * NPOS / 4) / 256, 256>>>(x, gamma, beta, out);
}

// round 15
// speedup vs baseline: 1.1642x; 1.1642x over previous
#include <cuda_runtime.h>
#include <cuda_fp16.h>
#include <cstdint>
#include <stdint.h>

#define BATCH 2
#define CH    256
#define CI    128
#define NPOS  8192
#define KT    64
#define NT    (NPOS/KT)

// ---------------- scratch (device globals; no allocation) ----------------
__device__ __align__(16) __half g_Wth[CI*CH];         // [ci][c] fp16
__device__ __align__(16) __half g_Wph[CI*CH];
__device__ __align__(16) __half g_Wgh[CI*CH];
__device__ __align__(16) __half g_Wwh[CH*CI];         // [o][ci] fp16
__device__ __align__(16) __half g_xh [BATCH*CH*NPOS]; // [b][c][n] fp16
__device__ __align__(16) __half g_Qhi[BATCH*NPOS*CI]; // [b][n][ci] (scaled by log2e)
__device__ __align__(16) __half g_Khi[BATCH*NPOS*CI]; // [b][m][ci]
__device__ __align__(16) __half g_Vh [BATCH*NPOS*CI]; // [b][m][ci]
__device__ __align__(16) __half g_Yth[BATCH*CI*NPOS]; // [b][ci][n] fp16
__device__ float g_WY[BATCH*CH*NPOS];   // [b][o][n]
__device__ float g_pS[128*CH];          // per-CTA channel partial sums
__device__ float g_pQ[128*CH];          // per-CTA channel partial sumsq
__device__ float g_mean[CH];
__device__ float g_rstd[CH];

// ---------------- helpers (baseline ISA only) ----------------
__device__ __forceinline__ uint32_t smem_u32(const void* p) {
    uint32_t a;
    asm("{ .reg .u64 t; cvta.to.shared.u64 t, %1; cvt.u32.u64 %0, t; }" : "=r"(a) : "l"(p));
    return a;
}
__device__ __forceinline__ void cp16(uint32_t d, const void* s) {
    asm volatile("cp.async.cg.shared.global [%0], [%1], 16;" :: "r"(d), "l"(s));
}
__device__ __forceinline__ void cp_commit()   { asm volatile("cp.async.commit_group;" ::: "memory"); }
__device__ __forceinline__ void cp_wait0()    { asm volatile("cp.async.wait_group 0;" ::: "memory"); }
__device__ __forceinline__ void cp_wait1()    { asm volatile("cp.async.wait_group 1;" ::: "memory"); }

__device__ __forceinline__ void ldm4(uint32_t& r0, uint32_t& r1, uint32_t& r2, uint32_t& r3, uint32_t a) {
    asm volatile("ldmatrix.sync.aligned.m8n8.x4.shared.b16 {%0,%1,%2,%3}, [%4];"
                 : "=r"(r0), "=r"(r1), "=r"(r2), "=r"(r3) : "r"(a));
}
__device__ __forceinline__ void ldm4t(uint32_t& r0, uint32_t& r1, uint32_t& r2, uint32_t& r3, uint32_t a) {
    asm volatile("ldmatrix.sync.aligned.m8n8.x4.trans.shared.b16 {%0,%1,%2,%3}, [%4];"
                 : "=r"(r0), "=r"(r1), "=r"(r2), "=r"(r3) : "r"(a));
}
#define MMA16816(c, a0,a1,a2,a3, b0,b1) \
    asm volatile("mma.sync.aligned.m16n8k16.row.col.f32.f16.f16.f32 " \
                 "{%0,%1,%2,%3},{%4,%5,%6,%7},{%8,%9},{%0,%1,%2,%3};" \
                 : "+f"((c)[0]), "+f"((c)[1]), "+f"((c)[2]), "+f"((c)[3]) \
                 : "r"(a0), "r"(a1), "r"(a2), "r"(a3), "r"(b0), "r"(b1))

__device__ __forceinline__ float ex2f(float x) {
    float r; asm("ex2.approx.f32 %0, %1;" : "=f"(r) : "f"(x)); return r;
}
__device__ __forceinline__ uint32_t packh2(float lo, float hi) {
    __half2 h = __floats2half2_rn(lo, hi);
    return *reinterpret_cast<uint32_t*>(&h);
}

// smem layout for attn (bytes)
#define QPITCH_B   272                      // 136 halves per row
#define QMAT_B     (128*QPITCH_B)           // 34816
#define KMAT_B     (64*QPITCH_B)            // 17408
#define KVBUF_B    (2*KMAT_B)               // KHI,V = 34816
#define SM_KV      QMAT_B                   // KV ring after Q region
#define DSM_BYTES  (QMAT_B + 3*KVBUF_B)     // 139264

// ---------------- K0: fused weight + x fp16 conversion ----------------
// work items: [0, 4*32768) = weights, [4*32768, ...) = x as float4
#define WCNT (4*CH*CI)                       // 131072
#define XCNT (BATCH*CH*NPOS/4)               // 1048576
__global__ __launch_bounds__(256) void cvt_all(
    const float* __restrict__ Wt, const float* __restrict__ Wp,
    const float* __restrict__ Wg, const float* __restrict__ Ww,
    const float* __restrict__ x)
{
    int idx = blockIdx.x * 256 + threadIdx.x;
    if (idx < WCNT) {
        int which = idx >> 15, e = idx & 32767;
        if (which == 0)      g_Wth[e] = __float2half_rn(Wt[e]);
        else if (which == 1) g_Wph[e] = __float2half_rn(Wp[e]);
        else if (which == 2) g_Wgh[e] = __float2half_rn(Wg[e]);
        else                 g_Wwh[e] = __float2half_rn(Ww[e]);
    } else {
        int i4 = idx - WCNT;
        if (i4 < XCNT) {
            float4 v = ((const float4*)x)[i4];
            __half2 a = __floats2half2_rn(v.x, v.y);
            __half2 b = __floats2half2_rn(v.z, v.w);
            uint2 u;
            u.x = *reinterpret_cast<uint32_t*>(&a);
            u.y = *reinterpret_cast<uint32_t*>(&b);
            ((uint2*)g_xh)[i4] = u;
        }
    }
}

// ---------------- K1: QKV projection via mma.sync ----------------
#define QK_WPITCH 528
#define QK_XPITCH 272
#define QK_WSH_B  (128*QK_WPITCH)   // 67584
#define QK_XSH_B  (256*QK_XPITCH)   // 69632
#define QK_DSM    (QK_WSH_B + QK_XSH_B)  // 137216

__global__ __launch_bounds__(256, 1) void qkv_mma(
    const float* __restrict__ bt, const float* __restrict__ bp,
    const float* __restrict__ bg)
{
    extern __shared__ __align__(16) char dsm[];
    const uint32_t wsh = smem_u32(dsm);
    const uint32_t xsh = wsh + QK_WSH_B;

    const int n0  = blockIdx.x * 128;
    const int b   = blockIdx.y;
    const int sel = blockIdx.z;
    const __half* Wh   = (sel == 0) ? g_Wth : (sel == 1) ? g_Wph : g_Wgh;
    const float*  bias = (sel == 0) ? bt : (sel == 1) ? bp : bg;
    const __half* xb   = &g_xh[(size_t)b * CH * NPOS];

    const int tid = threadIdx.x;
    const int w   = tid >> 5;
    const int lane = tid & 31;
    const int g   = lane >> 2;
    const int tq  = lane & 3;

#pragma unroll
    for (int it = 0; it < 16; it++) {
        int idx = tid + it * 256;
        int r = idx >> 5, s = idx & 31;
        cp16(wsh + (uint32_t)(r * QK_WPITCH + s * 16), Wh + (size_t)r * CH + s * 8);
    }
#pragma unroll
    for (int it = 0; it < 16; it++) {
        int idx = tid + it * 256;
        int r = idx >> 4, s = idx & 15;
        cp16(xsh + (uint32_t)(r * QK_XPITCH + s * 16), xb + (size_t)r * NPOS + n0 + s * 8);
    }
    cp_commit();
    cp_wait0();
    __syncthreads();

    const uint32_t a_base = wsh + (uint32_t)(16 * w + (lane & 15)) * QK_WPITCH
                          + (uint32_t)((lane >> 4) & 1) * 16;
    const int v_row = (lane & 7) + (((lane >> 3) & 1) << 3);
    const uint32_t v_c8 = (uint32_t)((lane >> 4) & 1) * 16;

    float c[16][4];
#pragma unroll
    for (int j = 0; j < 16; j++)
#pragma unroll
        for (int q = 0; q < 4; q++) c[j][q] = 0.f;

#pragma unroll
    for (int ks = 0; ks < 16; ks++) {
        uint32_t a0, a1, a2, a3;
        ldm4(a0, a1, a2, a3, a_base + (uint32_t)ks * 32);
        const uint32_t xrow = xsh + (uint32_t)(16 * ks + v_row) * QK_XPITCH + v_c8;
#pragma unroll
        for (int f = 0; f < 8; f++) {
            uint32_t b0, b1, b2, b3;
            ldm4t(b0, b1, b2, b3, xrow + (uint32_t)(f * 16) * 2);
            MMA16816(c[2*f],   a0, a1, a2, a3, b0, b1);
            MMA16816(c[2*f+1], a0, a1, a2, a3, b2, b3);
        }
    }

    __syncthreads();

    const float scale = (sel == 0) ? 1.4426950408889634f : 1.0f;
    const int ci0 = 16 * w + g, ci1 = ci0 + 8;
    const float b0v = bias[ci0], b1v = bias[ci1];
    __half* sT = (__half*)dsm;        // [128 n][136 halves pitch]
#pragma unroll
    for (int j = 0; j < 16; j++) {
        int n = (j >> 1) * 16 + (j & 1) * 8 + 2 * tq;
        sT[n * 136 + ci0]       = __float2half_rn((c[j][0] + b0v) * scale);
        sT[(n + 1) * 136 + ci0] = __float2half_rn((c[j][1] + b0v) * scale);
        sT[n * 136 + ci1]       = __float2half_rn((c[j][2] + b1v) * scale);
        sT[(n + 1) * 136 + ci1] = __float2half_rn((c[j][3] + b1v) * scale);
    }
    __syncthreads();

    __half* dst = ((sel == 0) ? g_Qhi : (sel == 1) ? g_Khi : g_Vh)
                + ((size_t)b * NPOS + n0) * CI;
#pragma unroll
    for (int it = 0; it < 8; it++) {
        int idx = tid + it * 256;
        int r = idx >> 4, s = idx & 15;
        *(uint4*)&dst[(size_t)r * CI + s * 8] = *(uint4*)&sT[r * 136 + s * 8];
    }
}

// ---------------- K2: flash attention, software-pipelined (round-13 version) ----------------
__global__ __launch_bounds__(256, 1) void attn_kernel()
{
    extern __shared__ __align__(16) char dsm[];
    const uint32_t tb  = smem_u32(dsm);
    const uint32_t kvb = tb + SM_KV;

    const int b   = blockIdx.y;
    const int n0  = blockIdx.x * 128;
    const int tid = threadIdx.x;
    const int w   = tid >> 5;
    const int lane = tid & 31;
    const int g   = lane >> 2;
    const int tq  = lane & 3;

    const int a_row = 16 * w + (lane & 15);
    const uint32_t a_off = (uint32_t)a_row * QPITCH_B + (uint32_t)((lane >> 4) & 1) * 16;
    const int b_row = (lane & 7) + ((lane >> 4) << 3);
    const uint32_t b_k8 = (uint32_t)((lane >> 3) & 1) * 16;
    const int v_row = (lane & 7) + (((lane >> 3) & 1) << 3);
    const uint32_t v_c8 = (uint32_t)((lane >> 4) & 1) * 16;

    const __half* khg = &g_Khi[(size_t)b * NPOS * CI];
    const __half* vg  = &g_Vh [(size_t)b * NPOS * CI];

    auto load_tile = [&](int t, int slot) {
        const int m0 = t * KT;
        const uint32_t kb = kvb + (uint32_t)slot * KVBUF_B;
#pragma unroll
        for (int it = 0; it < 8; it++) {
            int idx = tid + it * 256;
            int mat = idx >> 10;
            int r   = (idx & 1023) >> 4;
            int seg = idx & 15;
            const __half* src = (mat == 0 ? khg : vg) + ((size_t)(m0 + r)) * CI + seg * 8;
            cp16(kb + (uint32_t)(mat * KMAT_B + r * QPITCH_B + seg * 16), src);
        }
    };

    {
        const __half* qh = &g_Qhi[((size_t)b * NPOS + n0) * CI];
#pragma unroll
        for (int it = 0; it < 8; it++) {
            int idx = tid + it * 256;
            int r   = idx >> 4;
            int seg = idx & 15;
            cp16(tb + (uint32_t)(r * QPITCH_B + seg * 16), qh + (size_t)r * CI + seg * 8);
        }
    }
    load_tile(0, 0);
    cp_commit();
    load_tile(1, 1);
    cp_commit();
    cp_wait1();
    __syncthreads();

    uint32_t qr[8][4];
#pragma unroll
    for (int k8 = 0; k8 < 8; k8++)
        ldm4(qr[k8][0], qr[k8][1], qr[k8][2], qr[k8][3], tb + a_off + (uint32_t)k8 * 32);

    float c[8][4];
#pragma unroll
    for (int i = 0; i < 8; i++)
#pragma unroll
        for (int j = 0; j < 4; j++) c[i][j] = 0.f;
    {
        const uint32_t kb = kvb;
#pragma unroll
        for (int k8 = 0; k8 < 8; k8++) {
#pragma unroll
            for (int nj = 0; nj < 4; nj++) {
                uint32_t b0, b1, b2, b3;
                ldm4(b0, b1, b2, b3, kb + (uint32_t)(nj * 16 + b_row) * QPITCH_B
                                        + (uint32_t)k8 * 32 + b_k8);
                MMA16816(c[2*nj],   qr[k8][0], qr[k8][1], qr[k8][2], qr[k8][3], b0, b1);
                MMA16816(c[2*nj+1], qr[k8][0], qr[k8][1], qr[k8][2], qr[k8][3], b2, b3);
            }
        }
    }

    float O[16][4];
#pragma unroll
    for (int i = 0; i < 16; i++)
#pragma unroll
        for (int j = 0; j < 4; j++) O[i][j] = 0.f;
    float lsum0 = 0.f, lsum1 = 0.f;

#pragma unroll 1
    for (int t = 0; t < NT; t++) {
        const bool hasnext = (t + 1 < NT);

        uint32_t pk[8][2];
#pragma unroll
        for (int j = 0; j < 8; j++) {
            float e0 = ex2f(c[j][0]), e1 = ex2f(c[j][1]);
            float e2 = ex2f(c[j][2]), e3 = ex2f(c[j][3]);
            lsum0 += e0 + e1;
            lsum1 += e2 + e3;
            pk[j][0] = packh2(e0, e1);
            pk[j][1] = packh2(e2, e3);
        }

        cp_wait0();
        __syncthreads();
        if (t + 2 < NT) load_tile(t + 2, (t + 2) % 3);
        cp_commit();

        const uint32_t bufP = kvb + (uint32_t)(t % 3) * KVBUF_B;
        const uint32_t bufS = kvb + (uint32_t)((t + 1) % 3) * KVBUF_B;
        const uint32_t vb   = bufP + KMAT_B;

        float c2[8][4];
#pragma unroll
        for (int i = 0; i < 8; i++)
#pragma unroll
            for (int j = 0; j < 4; j++) c2[i][j] = 0.f;

#pragma unroll
        for (int step = 0; step < 8; step++) {
            if (hasnext) {
#pragma unroll
                for (int nj = 0; nj < 4; nj++) {
                    uint32_t b0, b1, b2, b3;
                    ldm4(b0, b1, b2, b3, bufS + (uint32_t)(nj * 16 + b_row) * QPITCH_B
                                            + (uint32_t)step * 32 + b_k8);
                    MMA16816(c2[2*nj],   qr[step][0], qr[step][1], qr[step][2], qr[step][3], b0, b1);
                    MMA16816(c2[2*nj+1], qr[step][0], qr[step][1], qr[step][2], qr[step][3], b2, b3);
                }
            }
            const int kk = step >> 1, ph = step & 1;
            const uint32_t a0 = pk[2*kk][0], a1 = pk[2*kk][1];
            const uint32_t a2 = pk[2*kk+1][0], a3 = pk[2*kk+1][1];
            const uint32_t vrow_off = (uint32_t)(kk * 16 + v_row) * QPITCH_B;
#pragma unroll
            for (int p = ph * 4; p < ph * 4 + 4; p++) {
                uint32_t b0, b1, b2, b3;
                ldm4t(b0, b1, b2, b3, vb + vrow_off + (uint32_t)(p * 16) * 2 + v_c8);
                MMA16816(O[2*p],   a0, a1, a2, a3, b0, b1);
                MMA16816(O[2*p+1], a0, a1, a2, a3, b2, b3);
            }
        }

#pragma unroll
        for (int i = 0; i < 8; i++)
#pragma unroll
            for (int j = 0; j < 4; j++) c[i][j] = c2[i][j];
    }

    lsum0 += __shfl_xor_sync(0xffffffffu, lsum0, 1);
    lsum0 += __shfl_xor_sync(0xffffffffu, lsum0, 2);
    lsum1 += __shfl_xor_sync(0xffffffffu, lsum1, 1);
    lsum1 += __shfl_xor_sync(0xffffffffu, lsum1, 2);
    const float linv0 = 1.f / lsum0, linv1 = 1.f / lsum1;

    __syncthreads();
    float* sO = (float*)dsm;     // [128][132] floats, 67584B
#pragma unroll
    for (int p = 0; p < 16; p++) {
        int col = p * 8 + 2 * tq;
        sO[(16 * w + g) * 132 + col]       = O[p][0] * linv0;
        sO[(16 * w + g) * 132 + col + 1]   = O[p][1] * linv0;
        sO[(16 * w + g + 8) * 132 + col]   = O[p][2] * linv1;
        sO[(16 * w + g + 8) * 132 + col+1] = O[p][3] * linv1;
    }
    __syncthreads();

    {
        const int ci   = tid >> 1;
        const int half = tid & 1;
        __half* dst = &g_Yth[((size_t)b * CI + ci) * NPOS + n0 + 64 * half];
#pragma unroll
        for (int r4 = 0; r4 < 16; r4++) {
            int r = 64 * half + r4 * 4;
            __half2 h01 = __floats2half2_rn(sO[(r + 0) * 132 + ci], sO[(r + 1) * 132 + ci]);
            __half2 h23 = __floats2half2_rn(sO[(r + 2) * 132 + ci], sO[(r + 3) * 132 + ci]);
            *(__half2*)&dst[r4 * 4]     = h01;
            *(__half2*)&dst[r4 * 4 + 2] = h23;
        }
    }
}

// ---------------- K3: wy = Ww.y + bw via mma.sync, + BN partials ----------------
#define WY_WPITCH 272
#define WY_YPITCH 272
#define WY_WSH_B  (256*WY_WPITCH)   // 69632
#define WY_YSH_B  (128*WY_YPITCH)   // 34816
#define WY_DSM    (WY_WSH_B + WY_YSH_B)

__global__ __launch_bounds__(256, 1) void wy_kernel(const float* __restrict__ bw)
{
    extern __shared__ __align__(16) char dsm[];
    const uint32_t wsh = smem_u32(dsm);
    const uint32_t ysh = wsh + WY_WSH_B;

    const int n0 = blockIdx.x * 128;
    const int b  = blockIdx.y;
    const int cta = b * 64 + blockIdx.x;
    const int tid = threadIdx.x;
    const int w   = tid >> 5;
    const int lane = tid & 31;
    const int g   = lane >> 2;
    const int tq  = lane & 3;

#pragma unroll
    for (int it = 0; it < 16; it++) {
        int idx = tid + it * 256;
        int r = idx >> 4, seg = idx & 15;
        cp16(wsh + (uint32_t)(r * WY_WPITCH + seg * 16), &g_Wwh[(size_t)r * CI + seg * 8]);
    }
    {
        const __half* yg = &g_Yth[(size_t)b * CI * NPOS + n0];
#pragma unroll
        for (int it = 0; it < 8; it++) {
            int idx = tid + it * 256;
            int r = idx >> 4, seg = idx & 15;
            cp16(ysh + (uint32_t)(r * WY_YPITCH + seg * 16), yg + (size_t)r * NPOS + seg * 8);
        }
    }
    cp_commit();
    cp_wait0();
    __syncthreads();

    const uint32_t a_base = wsh + (uint32_t)(32 * w + (lane & 15)) * WY_WPITCH
                          + (uint32_t)((lane >> 4) & 1) * 16;
    const int v_row = (lane & 7) + (((lane >> 3) & 1) << 3);
    const uint32_t v_c8 = (uint32_t)((lane >> 4) & 1) * 16;

    float c[2][16][4];
#pragma unroll
    for (int m = 0; m < 2; m++)
#pragma unroll
        for (int j = 0; j < 16; j++)
#pragma unroll
            for (int q = 0; q < 4; q++) c[m][j][q] = 0.f;

#pragma unroll
    for (int ks = 0; ks < 8; ks++) {
        uint32_t a0[4], a1[4];
        ldm4(a0[0], a0[1], a0[2], a0[3], a_base + (uint32_t)ks * 32);
        ldm4(a1[0], a1[1], a1[2], a1[3], a_base + 16u * WY_WPITCH + (uint32_t)ks * 32);
        const uint32_t yrow = ysh + (uint32_t)(16 * ks + v_row) * WY_YPITCH + v_c8;
#pragma unroll
        for (int f = 0; f < 8; f++) {
            uint32_t b0, b1, b2, b3;
            ldm4t(b0, b1, b2, b3, yrow + (uint32_t)(f * 16) * 2);
            MMA16816(c[0][2*f],   a0[0], a0[1], a0[2], a0[3], b0, b1);
            MMA16816(c[0][2*f+1], a0[0], a0[1], a0[2], a0[3], b2, b3);
            MMA16816(c[1][2*f],   a1[0], a1[1], a1[2], a1[3], b0, b1);
            MMA16816(c[1][2*f+1], a1[0], a1[1], a1[2], a1[3], b2, b3);
        }
    }

#pragma unroll
    for (int m = 0; m < 2; m++) {
        const int o0 = 32 * w + 16 * m;
        const float bias0 = bw[o0 + g];
        const float bias1 = bw[o0 + g + 8];
        float* d0 = &g_WY[((size_t)b * CH + o0 + g) * NPOS + n0];
        float* d1 = &g_WY[((size_t)b * CH + o0 + g + 8) * NPOS + n0];
        float sA = 0.f, qA = 0.f, sB = 0.f, qB = 0.f;
#pragma unroll
        for (int j = 0; j < 16; j++) {
            int nc = 8 * j + 2 * tq;
            float v0 = c[m][j][0] + bias0, v1 = c[m][j][1] + bias0;
            float v2 = c[m][j][2] + bias1, v3 = c[m][j][3] + bias1;
            *(float2*)&d0[nc] = make_float2(v0, v1);
            *(float2*)&d1[nc] = make_float2(v2, v3);
            sA += v0 + v1; qA += v0 * v0 + v1 * v1;
            sB += v2 + v3; qB += v2 * v2 + v3 * v3;
        }
        // reduce over the 4 lanes (tq) that share each row
        sA += __shfl_xor_sync(0xffffffffu, sA, 1);
        sA += __shfl_xor_sync(0xffffffffu, sA, 2);
        qA += __shfl_xor_sync(0xffffffffu, qA, 1);
        qA += __shfl_xor_sync(0xffffffffu, qA, 2);
        sB += __shfl_xor_sync(0xffffffffu, sB, 1);
        sB += __shfl_xor_sync(0xffffffffu, sB, 2);
        qB += __shfl_xor_sync(0xffffffffu, qB, 1);
        qB += __shfl_xor_sync(0xffffffffu, qB, 2);
        if (tq == 0) {
            g_pS[cta * CH + o0 + g]     = sA;
            g_pQ[cta * CH + o0 + g]     = qA;
            g_pS[cta * CH + o0 + g + 8] = sB;
            g_pQ[cta * CH + o0 + g + 8] = qB;
        }
    }
}

// ---------------- K4: reduce BN partials ----------------
__global__ __launch_bounds__(256) void bnstats2()
{
    const int o = threadIdx.x;
    float s = 0.f, q = 0.f;
#pragma unroll 4
    for (int i = 0; i < 128; i++) {
        s += g_pS[i * CH + o];
        q += g_pQ[i * CH + o];
    }
    float mean = s / (float)(BATCH * NPOS);
    float var  = q / (float)(BATCH * NPOS) - mean * mean;
    g_mean[o] = mean;
    g_rstd[o] = rsqrtf(var + 1e-5f);
}

// ---------------- K5: normalize + affine + residual ----------------
__global__ __launch_bounds__(256) void finalize_kernel(
    const float* __restrict__ x, const float* __restrict__ gamma,
    const float* __restrict__ beta, float* __restrict__ out)
{
    int i4 = blockIdx.x * 256 + threadIdx.x;
    int ch = (i4 >> 11) & (CH - 1);
    float sc = g_rstd[ch] * gamma[ch];
    float sh = beta[ch] - g_mean[ch] * sc;
    float4 w  = ((const float4*)g_WY)[i4];
    float4 xv = ((const float4*)x)[i4];
    float4 o;
    o.x = w.x * sc + sh + xv.x;
    o.y = w.y * sc + sh + xv.y;
    o.z = w.z * sc + sh + xv.z;
    o.w = w.w * sc + sh + xv.w;
    ((float4*)out)[i4] = o;
}

// ---------------- launch ----------------
extern "C" void kernel_launch(void* const* d_in, const int* in_sizes, int n_in,
                              void* d_out, int out_size)
{
    (void)in_sizes; (void)n_in; (void)out_size;
    const float* x     = (const float*)d_in[0];
    const float* Wt    = (const float*)d_in[1];
    const float* bt    = (const float*)d_in[2];
    const float* Wp    = (const float*)d_in[3];
    const float* bp    = (const float*)d_in[4];
    const float* Wg    = (const float*)d_in[5];
    const float* bg    = (const float*)d_in[6];
    const float* Ww    = (const float*)d_in[7];
    const float* bw    = (const float*)d_in[8];
    const float* gamma = (const float*)d_in[9];
    const float* beta  = (const float*)d_in[10];
    float* out = (float*)d_out;

    cvt_all<<<(WCNT + XCNT + 255) / 256, 256>>>(Wt, Wp, Wg, Ww, x);

    cudaFuncSetAttribute(qkv_mma, cudaFuncAttributeMaxDynamicSharedMemorySize, QK_DSM);
    qkv_mma<<<dim3(NPOS / 128, BATCH, 3), 256, QK_DSM>>>(bt, bp, bg);

    cudaFuncSetAttribute(attn_kernel, cudaFuncAttributeMaxDynamicSharedMemorySize, DSM_BYTES);
    attn_kernel<<<dim3(NPOS / 128, BATCH), 256, DSM_BYTES>>>();

    cudaFuncSetAttribute(wy_kernel, cudaFuncAttributeMaxDynamicSharedMemorySize, WY_DSM);
    wy_kernel<<<dim3(NPOS / 128, BATCH), 256, WY_DSM>>>(bw);

    bnstats2<<<1, 256>>>();
    finalize_kernel<<<(BATCH * CH * NPOS / 4) / 256, 256>>>(x, gamma, beta, out);
}

// round 16
// speedup vs baseline: 1.2179x; 1.0462x over previous
#include <cuda_runtime.h>
#include <cuda_fp16.h>
#include <cstdint>
#include <stdint.h>

#define BATCH 2
#define CH    256
#define CI    128
#define NPOS  8192
#define KT    64
#define NT    (NPOS/KT)

// ---------------- scratch (device globals; no allocation) ----------------
__device__ __align__(16) __half g_Wth[CI*CH];         // [ci][c] fp16
__device__ __align__(16) __half g_Wph[CI*CH];
__device__ __align__(16) __half g_Wgh[CI*CH];
__device__ __align__(16) __half g_Wwh[CH*CI];         // [o][ci] fp16
__device__ __align__(16) __half g_xh [BATCH*CH*NPOS]; // [b][c][n] fp16
__device__ __align__(16) __half g_Qhi[BATCH*NPOS*CI]; // [b][n][ci] (scaled by log2e)
__device__ __align__(16) __half g_Khi[BATCH*NPOS*CI]; // [b][m][ci]
__device__ __align__(16) __half g_Vh [BATCH*NPOS*CI]; // [b][m][ci]
__device__ float g_WY[BATCH*CH*NPOS];   // [b][o][n]
__device__ float g_pS[128*CH];          // per-CTA channel partial sums
__device__ float g_pQ[128*CH];          // per-CTA channel partial sumsq
__device__ float g_mean[CH];
__device__ float g_rstd[CH];

// ---------------- helpers (baseline ISA only) ----------------
__device__ __forceinline__ uint32_t smem_u32(const void* p) {
    uint32_t a;
    asm("{ .reg .u64 t; cvta.to.shared.u64 t, %1; cvt.u32.u64 %0, t; }" : "=r"(a) : "l"(p));
    return a;
}
__device__ __forceinline__ void cp16(uint32_t d, const void* s) {
    asm volatile("cp.async.cg.shared.global [%0], [%1], 16;" :: "r"(d), "l"(s));
}
__device__ __forceinline__ void cp_commit()   { asm volatile("cp.async.commit_group;" ::: "memory"); }
__device__ __forceinline__ void cp_wait0()    { asm volatile("cp.async.wait_group 0;" ::: "memory"); }
__device__ __forceinline__ void cp_wait1()    { asm volatile("cp.async.wait_group 1;" ::: "memory"); }

__device__ __forceinline__ void ldm4(uint32_t& r0, uint32_t& r1, uint32_t& r2, uint32_t& r3, uint32_t a) {
    asm volatile("ldmatrix.sync.aligned.m8n8.x4.shared.b16 {%0,%1,%2,%3}, [%4];"
                 : "=r"(r0), "=r"(r1), "=r"(r2), "=r"(r3) : "r"(a));
}
__device__ __forceinline__ void ldm4t(uint32_t& r0, uint32_t& r1, uint32_t& r2, uint32_t& r3, uint32_t a) {
    asm volatile("ldmatrix.sync.aligned.m8n8.x4.trans.shared.b16 {%0,%1,%2,%3}, [%4];"
                 : "=r"(r0), "=r"(r1), "=r"(r2), "=r"(r3) : "r"(a));
}
#define MMA16816(c, a0,a1,a2,a3, b0,b1) \
    asm volatile("mma.sync.aligned.m16n8k16.row.col.f32.f16.f16.f32 " \
                 "{%0,%1,%2,%3},{%4,%5,%6,%7},{%8,%9},{%0,%1,%2,%3};" \
                 : "+f"((c)[0]), "+f"((c)[1]), "+f"((c)[2]), "+f"((c)[3]) \
                 : "r"(a0), "r"(a1), "r"(a2), "r"(a3), "r"(b0), "r"(b1))

__device__ __forceinline__ float ex2f(float x) {
    float r; asm("ex2.approx.f32 %0, %1;" : "=f"(r) : "f"(x)); return r;
}
__device__ __forceinline__ uint32_t packh2(float lo, float hi) {
    __half2 h = __floats2half2_rn(lo, hi);
    return *reinterpret_cast<uint32_t*>(&h);
}

// smem layout for attn (bytes)
#define QPITCH_B   272                      // 136 halves per row
#define QMAT_B     (128*QPITCH_B)           // 34816
#define KMAT_B     (64*QPITCH_B)            // 17408
#define KVBUF_B    (2*KMAT_B)               // KHI,V = 34816
#define SM_KV      QMAT_B                   // KV ring after Q region
#define DSM_BYTES  (QMAT_B + 3*KVBUF_B)     // 139264

// ---------------- K0: fused weight + x fp16 conversion ----------------
#define WCNT (4*CH*CI)                       // 131072
#define XCNT (BATCH*CH*NPOS/4)               // 1048576
__global__ __launch_bounds__(256) void cvt_all(
    const float* __restrict__ Wt, const float* __restrict__ Wp,
    const float* __restrict__ Wg, const float* __restrict__ Ww,
    const float* __restrict__ x)
{
    int idx = blockIdx.x * 256 + threadIdx.x;
    if (idx < WCNT) {
        int which = idx >> 15, e = idx & 32767;
        if (which == 0)      g_Wth[e] = __float2half_rn(Wt[e]);
        else if (which == 1) g_Wph[e] = __float2half_rn(Wp[e]);
        else if (which == 2) g_Wgh[e] = __float2half_rn(Wg[e]);
        else                 g_Wwh[e] = __float2half_rn(Ww[e]);
    } else {
        int i4 = idx - WCNT;
        if (i4 < XCNT) {
            float4 v = ((const float4*)x)[i4];
            __half2 a = __floats2half2_rn(v.x, v.y);
            __half2 b = __floats2half2_rn(v.z, v.w);
            uint2 u;
            u.x = *reinterpret_cast<uint32_t*>(&a);
            u.y = *reinterpret_cast<uint32_t*>(&b);
            ((uint2*)g_xh)[i4] = u;
        }
    }
}

// ---------------- K1: QKV projection via mma.sync ----------------
#define QK_WPITCH 528
#define QK_XPITCH 272
#define QK_WSH_B  (128*QK_WPITCH)   // 67584
#define QK_XSH_B  (256*QK_XPITCH)   // 69632
#define QK_DSM    (QK_WSH_B + QK_XSH_B)  // 137216

__global__ __launch_bounds__(256, 1) void qkv_mma(
    const float* __restrict__ bt, const float* __restrict__ bp,
    const float* __restrict__ bg)
{
    extern __shared__ __align__(16) char dsm[];
    const uint32_t wsh = smem_u32(dsm);
    const uint32_t xsh = wsh + QK_WSH_B;

    const int n0  = blockIdx.x * 128;
    const int b   = blockIdx.y;
    const int sel = blockIdx.z;
    const __half* Wh   = (sel == 0) ? g_Wth : (sel == 1) ? g_Wph : g_Wgh;
    const float*  bias = (sel == 0) ? bt : (sel == 1) ? bp : bg;
    const __half* xb   = &g_xh[(size_t)b * CH * NPOS];

    const int tid = threadIdx.x;
    const int w   = tid >> 5;
    const int lane = tid & 31;
    const int g   = lane >> 2;
    const int tq  = lane & 3;

#pragma unroll
    for (int it = 0; it < 16; it++) {
        int idx = tid + it * 256;
        int r = idx >> 5, s = idx & 31;
        cp16(wsh + (uint32_t)(r * QK_WPITCH + s * 16), Wh + (size_t)r * CH + s * 8);
    }
#pragma unroll
    for (int it = 0; it < 16; it++) {
        int idx = tid + it * 256;
        int r = idx >> 4, s = idx & 15;
        cp16(xsh + (uint32_t)(r * QK_XPITCH + s * 16), xb + (size_t)r * NPOS + n0 + s * 8);
    }
    cp_commit();
    cp_wait0();
    __syncthreads();

    const uint32_t a_base = wsh + (uint32_t)(16 * w + (lane & 15)) * QK_WPITCH
                          + (uint32_t)((lane >> 4) & 1) * 16;
    const int v_row = (lane & 7) + (((lane >> 3) & 1) << 3);
    const uint32_t v_c8 = (uint32_t)((lane >> 4) & 1) * 16;

    float c[16][4];
#pragma unroll
    for (int j = 0; j < 16; j++)
#pragma unroll
        for (int q = 0; q < 4; q++) c[j][q] = 0.f;

#pragma unroll
    for (int ks = 0; ks < 16; ks++) {
        uint32_t a0, a1, a2, a3;
        ldm4(a0, a1, a2, a3, a_base + (uint32_t)ks * 32);
        const uint32_t xrow = xsh + (uint32_t)(16 * ks + v_row) * QK_XPITCH + v_c8;
#pragma unroll
        for (int f = 0; f < 8; f++) {
            uint32_t b0, b1, b2, b3;
            ldm4t(b0, b1, b2, b3, xrow + (uint32_t)(f * 16) * 2);
            MMA16816(c[2*f],   a0, a1, a2, a3, b0, b1);
            MMA16816(c[2*f+1], a0, a1, a2, a3, b2, b3);
        }
    }

    __syncthreads();

    const float scale = (sel == 0) ? 1.4426950408889634f : 1.0f;
    const int ci0 = 16 * w + g, ci1 = ci0 + 8;
    const float b0v = bias[ci0], b1v = bias[ci1];
    __half* sT = (__half*)dsm;        // [128 n][136 halves pitch]
#pragma unroll
    for (int j = 0; j < 16; j++) {
        int n = (j >> 1) * 16 + (j & 1) * 8 + 2 * tq;
        sT[n * 136 + ci0]       = __float2half_rn((c[j][0] + b0v) * scale);
        sT[(n + 1) * 136 + ci0] = __float2half_rn((c[j][1] + b0v) * scale);
        sT[n * 136 + ci1]       = __float2half_rn((c[j][2] + b1v) * scale);
        sT[(n + 1) * 136 + ci1] = __float2half_rn((c[j][3] + b1v) * scale);
    }
    __syncthreads();

    __half* dst = ((sel == 0) ? g_Qhi : (sel == 1) ? g_Khi : g_Vh)
                + ((size_t)b * NPOS + n0) * CI;
#pragma unroll
    for (int it = 0; it < 8; it++) {
        int idx = tid + it * 256;
        int r = idx >> 4, s = idx & 15;
        *(uint4*)&dst[(size_t)r * CI + s * 8] = *(uint4*)&sT[r * 136 + s * 8];
    }
}

// ---------------- K2: flash attention + fused wy projection ----------------
// grid (64, 2), 256 threads. attn mainloop = round-13 version; epilogue computes
// wy = Ww.y + bw directly from the y tile in smem and emits BN partials.
__global__ __launch_bounds__(256, 1) void attn_kernel(const float* __restrict__ bw)
{
    extern __shared__ __align__(16) char dsm[];
    const uint32_t tb  = smem_u32(dsm);
    const uint32_t kvb = tb + SM_KV;

    const int b   = blockIdx.y;
    const int n0  = blockIdx.x * 128;
    const int cta = b * 64 + blockIdx.x;
    const int tid = threadIdx.x;
    const int w   = tid >> 5;
    const int lane = tid & 31;
    const int g   = lane >> 2;
    const int tq  = lane & 3;

    const int a_row = 16 * w + (lane & 15);
    const uint32_t a_off = (uint32_t)a_row * QPITCH_B + (uint32_t)((lane >> 4) & 1) * 16;
    const int b_row = (lane & 7) + ((lane >> 4) << 3);
    const uint32_t b_k8 = (uint32_t)((lane >> 3) & 1) * 16;
    const int v_row = (lane & 7) + (((lane >> 3) & 1) << 3);
    const uint32_t v_c8 = (uint32_t)((lane >> 4) & 1) * 16;

    const __half* khg = &g_Khi[(size_t)b * NPOS * CI];
    const __half* vg  = &g_Vh [(size_t)b * NPOS * CI];

    auto load_tile = [&](int t, int slot) {
        const int m0 = t * KT;
        const uint32_t kb = kvb + (uint32_t)slot * KVBUF_B;
#pragma unroll
        for (int it = 0; it < 8; it++) {
            int idx = tid + it * 256;
            int mat = idx >> 10;
            int r   = (idx & 1023) >> 4;
            int seg = idx & 15;
            const __half* src = (mat == 0 ? khg : vg) + ((size_t)(m0 + r)) * CI + seg * 8;
            cp16(kb + (uint32_t)(mat * KMAT_B + r * QPITCH_B + seg * 16), src);
        }
    };

    {
        const __half* qh = &g_Qhi[((size_t)b * NPOS + n0) * CI];
#pragma unroll
        for (int it = 0; it < 8; it++) {
            int idx = tid + it * 256;
            int r   = idx >> 4;
            int seg = idx & 15;
            cp16(tb + (uint32_t)(r * QPITCH_B + seg * 16), qh + (size_t)r * CI + seg * 8);
        }
    }
    load_tile(0, 0);
    cp_commit();
    load_tile(1, 1);
    cp_commit();
    cp_wait1();
    __syncthreads();

    uint32_t qr[8][4];
#pragma unroll
    for (int k8 = 0; k8 < 8; k8++)
        ldm4(qr[k8][0], qr[k8][1], qr[k8][2], qr[k8][3], tb + a_off + (uint32_t)k8 * 32);

    float c[8][4];
#pragma unroll
    for (int i = 0; i < 8; i++)
#pragma unroll
        for (int j = 0; j < 4; j++) c[i][j] = 0.f;
    {
        const uint32_t kb = kvb;
#pragma unroll
        for (int k8 = 0; k8 < 8; k8++) {
#pragma unroll
            for (int nj = 0; nj < 4; nj++) {
                uint32_t b0, b1, b2, b3;
                ldm4(b0, b1, b2, b3, kb + (uint32_t)(nj * 16 + b_row) * QPITCH_B
                                        + (uint32_t)k8 * 32 + b_k8);
                MMA16816(c[2*nj],   qr[k8][0], qr[k8][1], qr[k8][2], qr[k8][3], b0, b1);
                MMA16816(c[2*nj+1], qr[k8][0], qr[k8][1], qr[k8][2], qr[k8][3], b2, b3);
            }
        }
    }

    float O[16][4];
#pragma unroll
    for (int i = 0; i < 16; i++)
#pragma unroll
        for (int j = 0; j < 4; j++) O[i][j] = 0.f;
    float lsum0 = 0.f, lsum1 = 0.f;

#pragma unroll 1
    for (int t = 0; t < NT; t++) {
        const bool hasnext = (t + 1 < NT);

        uint32_t pk[8][2];
#pragma unroll
        for (int j = 0; j < 8; j++) {
            float e0 = ex2f(c[j][0]), e1 = ex2f(c[j][1]);
            float e2 = ex2f(c[j][2]), e3 = ex2f(c[j][3]);
            lsum0 += e0 + e1;
            lsum1 += e2 + e3;
            pk[j][0] = packh2(e0, e1);
            pk[j][1] = packh2(e2, e3);
        }

        cp_wait0();
        __syncthreads();
        if (t + 2 < NT) load_tile(t + 2, (t + 2) % 3);
        cp_commit();

        const uint32_t bufP = kvb + (uint32_t)(t % 3) * KVBUF_B;
        const uint32_t bufS = kvb + (uint32_t)((t + 1) % 3) * KVBUF_B;
        const uint32_t vb   = bufP + KMAT_B;

        float c2[8][4];
#pragma unroll
        for (int i = 0; i < 8; i++)
#pragma unroll
            for (int j = 0; j < 4; j++) c2[i][j] = 0.f;

#pragma unroll
        for (int step = 0; step < 8; step++) {
            if (hasnext) {
#pragma unroll
                for (int nj = 0; nj < 4; nj++) {
                    uint32_t b0, b1, b2, b3;
                    ldm4(b0, b1, b2, b3, bufS + (uint32_t)(nj * 16 + b_row) * QPITCH_B
                                            + (uint32_t)step * 32 + b_k8);
                    MMA16816(c2[2*nj],   qr[step][0], qr[step][1], qr[step][2], qr[step][3], b0, b1);
                    MMA16816(c2[2*nj+1], qr[step][0], qr[step][1], qr[step][2], qr[step][3], b2, b3);
                }
            }
            const int kk = step >> 1, ph = step & 1;
            const uint32_t a0 = pk[2*kk][0], a1 = pk[2*kk][1];
            const uint32_t a2 = pk[2*kk+1][0], a3 = pk[2*kk+1][1];
            const uint32_t vrow_off = (uint32_t)(kk * 16 + v_row) * QPITCH_B;
#pragma unroll
            for (int p = ph * 4; p < ph * 4 + 4; p++) {
                uint32_t b0, b1, b2, b3;
                ldm4t(b0, b1, b2, b3, vb + vrow_off + (uint32_t)(p * 16) * 2 + v_c8);
                MMA16816(O[2*p],   a0, a1, a2, a3, b0, b1);
                MMA16816(O[2*p+1], a0, a1, a2, a3, b2, b3);
            }
        }

#pragma unroll
        for (int i = 0; i < 8; i++)
#pragma unroll
            for (int j = 0; j < 4; j++) c[i][j] = c2[i][j];
    }

    // ---- epilogue: y tile -> smem fp16, Ww -> smem, wy MMA, BN partials ----
    lsum0 += __shfl_xor_sync(0xffffffffu, lsum0, 1);
    lsum0 += __shfl_xor_sync(0xffffffffu, lsum0, 2);
    lsum1 += __shfl_xor_sync(0xffffffffu, lsum1, 1);
    lsum1 += __shfl_xor_sync(0xffffffffu, lsum1, 2);
    const float linv0 = 1.f / lsum0, linv1 = 1.f / lsum1;

    __syncthreads();   // all warps done reading KV ring

    // Ww fp16 [256 o][128 ci] -> smem at +QMAT_B (overwrites ring slots 0-1)
    const uint32_t wwsh = tb + QMAT_B;
#pragma unroll
    for (int it = 0; it < 16; it++) {
        int idx = tid + it * 256;
        int r = idx >> 4, s = idx & 15;
        cp16(wwsh + (uint32_t)(r * QPITCH_B + s * 16), &g_Wwh[(size_t)r * CI + s * 8]);
    }
    cp_commit();

    // y tile fp16 [128 n][136 halves pitch] into Q region (dead after hoist)
    __half* sY = (__half*)dsm;
    {
        const int r0 = 16 * w + g;
#pragma unroll
        for (int p = 0; p < 16; p++) {
            int col = p * 8 + 2 * tq;
            *(__half2*)&sY[r0 * 136 + col]       = __floats2half2_rn(O[p][0] * linv0, O[p][1] * linv0);
            *(__half2*)&sY[(r0 + 8) * 136 + col] = __floats2half2_rn(O[p][2] * linv1, O[p][3] * linv1);
        }
    }
    cp_wait0();
    __syncthreads();

    // wy = Ww . y : A = Ww rows (o, k contiguous), B = y[n][ci] via non-trans ldm4
    const uint32_t wa_base = wwsh + (uint32_t)(32 * w + (lane & 15)) * QPITCH_B
                           + (uint32_t)((lane >> 4) & 1) * 16;
    float cw[2][16][4];
#pragma unroll
    for (int m = 0; m < 2; m++)
#pragma unroll
        for (int j = 0; j < 16; j++)
#pragma unroll
            for (int q = 0; q < 4; q++) cw[m][j][q] = 0.f;

#pragma unroll
    for (int ks = 0; ks < 8; ks++) {
        uint32_t a0[4], a1[4];
        ldm4(a0[0], a0[1], a0[2], a0[3], wa_base + (uint32_t)ks * 32);
        ldm4(a1[0], a1[1], a1[2], a1[3], wa_base + 16u * QPITCH_B + (uint32_t)ks * 32);
#pragma unroll
        for (int f = 0; f < 8; f++) {
            uint32_t b0, b1, b2, b3;
            ldm4(b0, b1, b2, b3, tb + (uint32_t)(f * 16 + b_row) * QPITCH_B
                                    + (uint32_t)ks * 32 + b_k8);
            MMA16816(cw[0][2*f],   a0[0], a0[1], a0[2], a0[3], b0, b1);
            MMA16816(cw[0][2*f+1], a0[0], a0[1], a0[2], a0[3], b2, b3);
            MMA16816(cw[1][2*f],   a1[0], a1[1], a1[2], a1[3], b0, b1);
            MMA16816(cw[1][2*f+1], a1[0], a1[1], a1[2], a1[3], b2, b3);
        }
    }

#pragma unroll
    for (int m = 0; m < 2; m++) {
        const int o0 = 32 * w + 16 * m;
        const float bias0 = bw[o0 + g];
        const float bias1 = bw[o0 + g + 8];
        float* d0 = &g_WY[((size_t)b * CH + o0 + g) * NPOS + n0];
        float* d1 = &g_WY[((size_t)b * CH + o0 + g + 8) * NPOS + n0];
        float sA = 0.f, qA = 0.f, sB = 0.f, qB = 0.f;
#pragma unroll
        for (int j = 0; j < 16; j++) {
            int nc = 8 * j + 2 * tq;
            float v0 = cw[m][j][0] + bias0, v1 = cw[m][j][1] + bias0;
            float v2 = cw[m][j][2] + bias1, v3 = cw[m][j][3] + bias1;
            *(float2*)&d0[nc] = make_float2(v0, v1);
            *(float2*)&d1[nc] = make_float2(v2, v3);
            sA += v0 + v1; qA += v0 * v0 + v1 * v1;
            sB += v2 + v3; qB += v2 * v2 + v3 * v3;
        }
        sA += __shfl_xor_sync(0xffffffffu, sA, 1);
        sA += __shfl_xor_sync(0xffffffffu, sA, 2);
        qA += __shfl_xor_sync(0xffffffffu, qA, 1);
        qA += __shfl_xor_sync(0xffffffffu, qA, 2);
        sB += __shfl_xor_sync(0xffffffffu, sB, 1);
        sB += __shfl_xor_sync(0xffffffffu, sB, 2);
        qB += __shfl_xor_sync(0xffffffffu, qB, 1);
        qB += __shfl_xor_sync(0xffffffffu, qB, 2);
        if (tq == 0) {
            g_pS[cta * CH + o0 + g]     = sA;
            g_pQ[cta * CH + o0 + g]     = qA;
            g_pS[cta * CH + o0 + g + 8] = sB;
            g_pQ[cta * CH + o0 + g + 8] = qB;
        }
    }
}

// ---------------- K3: reduce BN partials (parallel) ----------------
__global__ __launch_bounds__(256) void bnstats2()
{
    const int tid = threadIdx.x;
    const int ty = tid >> 5, lane = tid & 31;
    const int o = blockIdx.x * 8 + ty;
    float s = 0.f, q = 0.f;
#pragma unroll
    for (int i = lane; i < 128; i += 32) {
        s += g_pS[i * CH + o];
        q += g_pQ[i * CH + o];
    }
#pragma unroll
    for (int off = 16; off; off >>= 1) {
        s += __shfl_xor_sync(0xffffffffu, s, off);
        q += __shfl_xor_sync(0xffffffffu, q, off);
    }
    if (lane == 0) {
        float mean = s / (float)(BATCH * NPOS);
        float var  = q / (float)(BATCH * NPOS) - mean * mean;
        g_mean[o] = mean;
        g_rstd[o] = rsqrtf(var + 1e-5f);
    }
}

// ---------------- K4: normalize + affine + residual ----------------
__global__ __launch_bounds__(256) void finalize_kernel(
    const float* __restrict__ x, const float* __restrict__ gamma,
    const float* __restrict__ beta, float* __restrict__ out)
{
    int i4 = blockIdx.x * 256 + threadIdx.x;
    int ch = (i4 >> 11) & (CH - 1);
    float sc = g_rstd[ch] * gamma[ch];
    float sh = beta[ch] - g_mean[ch] * sc;
    float4 w  = ((const float4*)g_WY)[i4];
    float4 xv = ((const float4*)x)[i4];
    float4 o;
    o.x = w.x * sc + sh + xv.x;
    o.y = w.y * sc + sh + xv.y;
    o.z = w.z * sc + sh + xv.z;
    o.w = w.w * sc + sh + xv.w;
    ((float4*)out)[i4] = o;
}

// ---------------- launch ----------------
extern "C" void kernel_launch(void* const* d_in, const int* in_sizes, int n_in,
                              void* d_out, int out_size)
{
    (void)in_sizes; (void)n_in; (void)out_size;
    const float* x     = (const float*)d_in[0];
    const float* Wt    = (const float*)d_in[1];
    const float* bt    = (const float*)d_in[2];
    const float* Wp    = (const float*)d_in[3];
    const float* bp    = (const float*)d_in[4];
    const float* Wg    = (const float*)d_in[5];
    const float* bg    = (const float*)d_in[6];
    const float* Ww    = (const float*)d_in[7];
    const float* bw    = (const float*)d_in[8];
    const float* gamma = (const float*)d_in[9];
    const float* beta  = (const float*)d_in[10];
    float* out = (float*)d_out;

    cvt_all<<<(WCNT + XCNT + 255) / 256, 256>>>(Wt, Wp, Wg, Ww, x);

    cudaFuncSetAttribute(qkv_mma, cudaFuncAttributeMaxDynamicSharedMemorySize, QK_DSM);
    qkv_mma<<<dim3(NPOS / 128, BATCH, 3), 256, QK_DSM>>>(bt, bp, bg);

    cudaFuncSetAttribute(attn_kernel, cudaFuncAttributeMaxDynamicSharedMemorySize, DSM_BYTES);
    attn_kernel<<<dim3(NPOS / 128, BATCH), 256, DSM_BYTES>>>(bw);

    bnstats2<<<CH / 8, 256>>>();
    finalize_kernel<<<(BATCH * CH * NPOS / 4) / 256, 256>>>(x, gamma, beta, out);
}